// round 3
// baseline (speedup 1.0000x reference)
#include <cuda_runtime.h>

#define NB 16
#define NL 1024
#define NH 8
#define NE 64
#define NM 64
#define NBH (NB*NH)
#define HE 512
#define SCALE_F 3.814697265625e-06f  // 1/(512*512)

typedef unsigned long long u64;

// ---------------- packed f32x2 helpers ----------------
__device__ __forceinline__ u64 pk2(float x, float y) {
    u64 r;
    asm("mov.b64 %0, {%1, %2};" : "=l"(r) : "r"(__float_as_uint(x)), "r"(__float_as_uint(y)));
    return r;
}
__device__ __forceinline__ void upk2(u64 v, float& x, float& y) {
    unsigned a, b;
    asm("mov.b64 {%0, %1}, %2;" : "=r"(a), "=r"(b) : "l"(v));
    x = __uint_as_float(a); y = __uint_as_float(b);
}
__device__ __forceinline__ u64 f2(u64 a, u64 b, u64 c) {
    u64 d; asm("fma.rn.f32x2 %0, %1, %2, %3;" : "=l"(d) : "l"(a), "l"(b), "l"(c)); return d;
}
__device__ __forceinline__ u64 s2(u64 a, u64 b) {
    u64 d; asm("sub.rn.f32x2 %0, %1, %2;" : "=l"(d) : "l"(a), "l"(b)); return d;
}
__device__ __forceinline__ u64 m2(u64 a, u64 b) {
    u64 d; asm("mul.rn.f32x2 %0, %1, %2;" : "=l"(d) : "l"(a), "l"(b)); return d;
}

// ---------------- scratch (static device globals) ----------------
static __device__ float g_Mbuf[NBH*NE*NE];   // [bh][e][o]
static __device__ float g_ksum[NBH*NE];
static __device__ float g_vsum[NBH*NE];
static __device__ float g_Xr[NBH*NE*NM];     // [bh][e][m]
static __device__ float g_Xi[NBH*NE*NM];
static __device__ float g_Yr[NBH*NE*NM];     // [bh][o][m], pre-scaled c_m/2048
static __device__ float g_Yi[NBH*NE*NM];

// ===================== kernel A: k/v stats (M, ksum, vsum) =====================
__global__ void __launch_bounds__(256) k_stats(const float* __restrict__ kin,
                                               const float* __restrict__ vin) {
    const int bh = blockIdx.x;
    const int b = bh >> 3, h = bh & 7;
    const int t = threadIdx.x;
    __shared__ __align__(16) float2 sk[8][NE];   // (k,k) dup
    __shared__ __align__(16) float  sv[8][NE];
    const int e0 = (t >> 4) << 2;
    const int d0 = (t & 15) << 2;
    u64 acc[4][2] = {};
    float ka = 0.f, va = 0.f;
    const int base = b * NL * HE + h * NE;
    for (int s0 = 0; s0 < NL; s0 += 8) {
        __syncthreads();
        #pragma unroll
        for (int r = 0; r < 2; ++r) {
            int idx = r * 256 + t;
            int ss = idx >> 6, e = idx & 63;
            int g = base + (s0 + ss) * HE + e;
            float kv = kin[g];
            sk[ss][e] = make_float2(kv, kv);
            sv[ss][e] = vin[g];
        }
        __syncthreads();
        #pragma unroll
        for (int ss = 0; ss < 8; ++ss) {
            ulonglong2 vv = *(const ulonglong2*)&sv[ss][d0];
            #pragma unroll
            for (int i = 0; i < 4; ++i) {
                u64 kb = *(const u64*)&sk[ss][e0 + i];
                acc[i][0] = f2(kb, vv.x, acc[i][0]);
                acc[i][1] = f2(kb, vv.y, acc[i][1]);
            }
        }
        if (t < 64) {
            #pragma unroll
            for (int ss = 0; ss < 8; ++ss) { ka += sk[ss][t].x; va += sv[ss][t]; }
        }
    }
    float* Mo = g_Mbuf + bh * (NE*NE);
    #pragma unroll
    for (int i = 0; i < 4; ++i) {
        *(u64*)&Mo[(e0+i)*NE + d0]     = acc[i][0];
        *(u64*)&Mo[(e0+i)*NE + d0 + 2] = acc[i][1];
    }
    if (t < 64) { g_ksum[bh*NE + t] = ka; g_vsum[bh*NE + t] = va; }
}

// ===================== kernel B: forward truncated DFT of q =====================
// Xr[e,m] = sum_l q[l,e] cos(2pi m l/1024); Xi[e,m] = -sum_l q[l,e] sin(...)
__global__ void __launch_bounds__(256) k_fdft(const float* __restrict__ q) {
    const int bh = blockIdx.x;
    const int b = bh >> 3, h = bh & 7;
    const int t = threadIdx.x;
    __shared__ __align__(16) float sq[64][NE];
    __shared__ __align__(16) float4 tw4[1024];   // (c, c, -s, -s)
    for (int j = t; j < 1024; j += 256) {
        float s, c;
        sincospif((float)j * (1.0f/512.0f), &s, &c);
        tw4[j] = make_float4(c, c, -s, -s);
    }
    const int e0 = (t >> 4) << 2;                      // 4 e's = 2 packed pairs
    const int m0 = blockIdx.y * 32 + ((t & 15) << 1);  // 2 m's
    u64 xr[2][2] = {}, xi[2][2] = {};                  // [e-pair][mm]
    int jj[2] = {0, 0};
    const int base = b * NL * HE + h * NE;
    for (int l0 = 0; l0 < NL; l0 += 64) {
        __syncthreads();
        const float4* qg = (const float4*)(q + base + l0 * HE);
        #pragma unroll
        for (int r = 0; r < 4; ++r) {
            int f = r * 256 + t;
            int row = f >> 4, c4 = f & 15;
            ((float4*)sq)[row*16 + c4] = qg[row*128 + c4];
        }
        __syncthreads();
        #pragma unroll 4
        for (int l = 0; l < 64; ++l) {
            ulonglong2 qv = *(const ulonglong2*)&sq[l][e0];
            #pragma unroll
            for (int mm = 0; mm < 2; ++mm) {
                ulonglong2 w = *(const ulonglong2*)&tw4[jj[mm]];
                jj[mm] = (jj[mm] + m0 + mm) & 1023;
                xr[0][mm] = f2(qv.x, w.x, xr[0][mm]);
                xi[0][mm] = f2(qv.x, w.y, xi[0][mm]);
                xr[1][mm] = f2(qv.y, w.x, xr[1][mm]);
                xi[1][mm] = f2(qv.y, w.y, xi[1][mm]);
            }
        }
    }
    float* Xro = g_Xr + bh * (NE*NM);
    float* Xio = g_Xi + bh * (NE*NM);
    #pragma unroll
    for (int p = 0; p < 2; ++p)
        #pragma unroll
        for (int mm = 0; mm < 2; ++mm) {
            float a, bb; upk2(xr[p][mm], a, bb);
            Xro[(e0 + 2*p)*NM + m0 + mm]     = a;
            Xro[(e0 + 2*p + 1)*NM + m0 + mm] = bb;
            float cc, dd; upk2(xi[p][mm], cc, dd);
            Xio[(e0 + 2*p)*NM + m0 + mm]     = cc;
            Xio[(e0 + 2*p + 1)*NM + m0 + mm] = dd;
        }
}

// ===================== kernel C: per-mode complex mix Y = X * W =====================
__global__ void __launch_bounds__(512) k_mix(const float* __restrict__ wre,
                                             const float* __restrict__ wim) {
    const int h  = blockIdx.x >> 4;
    const int m0 = (blockIdx.x & 15) << 2;
    const int t = threadIdx.x;
    const int b  = t >> 5;
    const int o0 = (t & 31) << 1;
    const int bh = b * NH + h;
    u64 ar[2][2] = {}, br[2][2] = {}, ai[2][2] = {};
    const float* xrp = g_Xr + bh * (NE*NM) + m0;
    const float* xip = g_Xi + bh * (NE*NM) + m0;
    const float* wrp = wre + ((h*NE)*NE + o0) * NM + m0;
    const float* wip = wim + ((h*NE)*NE + o0) * NM + m0;
    for (int i = 0; i < NE; ++i) {
        ulonglong2 X = *(const ulonglong2*)xrp;  xrp += NM;
        ulonglong2 Z = *(const ulonglong2*)xip;  xip += NM;
        #pragma unroll
        for (int oo = 0; oo < 2; ++oo) {
            ulonglong2 Wr = *(const ulonglong2*)(wrp + oo*NM);
            ulonglong2 Wi = *(const ulonglong2*)(wip + oo*NM);
            ar[oo][0] = f2(X.x, Wr.x, ar[oo][0]);
            ar[oo][1] = f2(X.y, Wr.y, ar[oo][1]);
            br[oo][0] = f2(Z.x, Wi.x, br[oo][0]);
            br[oo][1] = f2(Z.y, Wi.y, br[oo][1]);
            ai[oo][0] = f2(X.x, Wi.x, f2(Z.x, Wr.x, ai[oo][0]));
            ai[oo][1] = f2(X.y, Wi.y, f2(Z.y, Wr.y, ai[oo][1]));
        }
        wrp += NE*NM; wip += NE*NM;
    }
    const float c2 = 2.0f / 2048.0f;
    const u64 sc0 = pk2((m0 == 0) ? (1.0f/2048.0f) : c2, c2);
    const u64 sc1 = pk2(c2, c2);
    #pragma unroll
    for (int oo = 0; oo < 2; ++oo) {
        ulonglong2 rr, ii;
        rr.x = m2(s2(ar[oo][0], br[oo][0]), sc0);
        rr.y = m2(s2(ar[oo][1], br[oo][1]), sc1);
        ii.x = m2(ai[oo][0], sc0);
        ii.y = m2(ai[oo][1], sc1);
        *(ulonglong2*)(g_Yr + (bh*NE + o0 + oo)*NM + m0) = rr;
        *(ulonglong2*)(g_Yi + (bh*NE + o0 + oo)*NM + m0) = ii;
    }
}

// ===================== kernel D1: linearized local attention =====================
// out = 0.5*(vsum[o] + SCALE*sum_e q[l,e] M[e,o]) / (1024 + SCALE*q[l,:].ksum)
__global__ void __launch_bounds__(256) k_local(const float* __restrict__ q,
                                               float* __restrict__ out) {
    const int bh = blockIdx.x;
    const int b = bh >> 3, h = bh & 7;
    const int t = threadIdx.x;
    __shared__ __align__(16) float sM[NE*NE];
    __shared__ __align__(16) float sq[64][NE];
    __shared__ float sks[NE];
    __shared__ float svs[NE];
    const float* Mi = g_Mbuf + bh*(NE*NE);
    for (int idx = t; idx < NE*NE; idx += 256) sM[idx] = Mi[idx];
    if (t < NE) { sks[t] = g_ksum[bh*NE+t]; svs[t] = g_vsum[bh*NE+t]; }
    const int og = t & 15, lg = t >> 4;
    const int o0 = og << 2;
    const int base  = b * NL * HE + h * NE;
    const int lbase = blockIdx.y * 512;
    for (int l0 = lbase; l0 < lbase + 512; l0 += 64) {
        __syncthreads();
        const float4* qg = (const float4*)(q + base + l0*HE);
        #pragma unroll
        for (int r = 0; r < 4; ++r) {
            int f = r*256 + t;
            int row = f >> 4, c4 = f & 15;
            ((float4*)sq)[row*16+c4] = qg[row*128 + c4];
        }
        __syncthreads();
        u64 acc[4][2] = {};
        float z[4] = {};
        #pragma unroll 2
        for (int e = 0; e < NE; ++e) {
            ulonglong2 mv = *(const ulonglong2*)&sM[e*NE + o0];
            float ks = sks[e];
            #pragma unroll
            for (int ll = 0; ll < 4; ++ll) {
                float qs = sq[lg*4+ll][e];
                u64 qb = pk2(qs, qs);
                acc[ll][0] = f2(qb, mv.x, acc[ll][0]);
                acc[ll][1] = f2(qb, mv.y, acc[ll][1]);
                z[ll] = fmaf(qs, ks, z[ll]);
            }
        }
        #pragma unroll
        for (int ll = 0; ll < 4; ++ll) {
            int l = l0 + lg*4 + ll;
            float Z = 1024.0f + SCALE_F * z[ll];
            float inv = 0.5f / Z;
            float a0, a1, a2, a3;
            upk2(acc[ll][0], a0, a1);
            upk2(acc[ll][1], a2, a3);
            float4 ov;
            ov.x = (svs[o0+0] + SCALE_F*a0) * inv;
            ov.y = (svs[o0+1] + SCALE_F*a1) * inv;
            ov.z = (svs[o0+2] + SCALE_F*a2) * inv;
            ov.w = (svs[o0+3] + SCALE_F*a3) * inv;
            *(float4*)(out + (b*NL + l)*HE + h*NE + o0) = ov;
        }
    }
}

// ===================== kernel D2: inverse truncated DFT, add to out =====================
// out[l,o] += sum_m Yr'[o,m]*cos(2pi m l/1024) - Yi'[o,m]*sin(...)
__global__ void __launch_bounds__(256) k_spec(float* __restrict__ out) {
    const int bh = blockIdx.x;
    const int b = bh >> 3, h = bh & 7;
    const int t = threadIdx.x;
    __shared__ __align__(16) float sYr[64*64];
    __shared__ __align__(16) float sYi[64*64];
    __shared__ __align__(16) float4 tw4[1024];   // (c, c, -s, -s)
    for (int j = t; j < 1024; j += 256) {
        float s, c;
        sincospif((float)j * (1.0f/512.0f), &s, &c);
        tw4[j] = make_float4(c, c, -s, -s);
    }
    const float* Yrb = g_Yr + bh*(NE*NM);
    const float* Yib = g_Yi + bh*(NE*NM);
    for (int idx = t; idx < NE*NM; idx += 256) {
        int o = idx >> 6, m = idx & 63;
        sYr[m*64 + o] = Yrb[idx];
        sYi[m*64 + o] = Yib[idx];
    }
    __syncthreads();
    const int og = t & 15, lg = t >> 4;
    const int o0 = og << 2;
    const int lbase = blockIdx.y * 512;
    for (int l0 = lbase; l0 < lbase + 512; l0 += 64) {
        u64 acc[4][2] = {};
        int lglob[4], jj[4];
        #pragma unroll
        for (int ll = 0; ll < 4; ++ll) { lglob[ll] = l0 + lg*4 + ll; jj[ll] = 0; }
        #pragma unroll 2
        for (int m = 0; m < NM; ++m) {
            ulonglong2 yr = *(const ulonglong2*)&sYr[m*64 + o0];
            ulonglong2 yi = *(const ulonglong2*)&sYi[m*64 + o0];
            #pragma unroll
            for (int ll = 0; ll < 4; ++ll) {
                ulonglong2 w = *(const ulonglong2*)&tw4[jj[ll]];
                jj[ll] = (jj[ll] + lglob[ll]) & 1023;
                acc[ll][0] = f2(yr.x, w.x, f2(yi.x, w.y, acc[ll][0]));
                acc[ll][1] = f2(yr.y, w.x, f2(yi.y, w.y, acc[ll][1]));
            }
        }
        #pragma unroll
        for (int ll = 0; ll < 4; ++ll) {
            float* op = out + (b*NL + lglob[ll])*HE + h*NE + o0;
            float4 cur = *(const float4*)op;
            float a0, a1, a2, a3;
            upk2(acc[ll][0], a0, a1);
            upk2(acc[ll][1], a2, a3);
            cur.x += a0; cur.y += a1; cur.z += a2; cur.w += a3;
            *(float4*)op = cur;
        }
    }
}

// ===================== launch =====================
extern "C" void kernel_launch(void* const* d_in, const int* in_sizes, int n_in,
                              void* d_out, int out_size) {
    (void)in_sizes; (void)n_in; (void)out_size;
    const float* q   = (const float*)d_in[0];
    const float* k   = (const float*)d_in[1];
    const float* v   = (const float*)d_in[2];
    // d_in[3] = mask (present -> reference applies no masking); unused
    const float* wre = (const float*)d_in[4];
    const float* wim = (const float*)d_in[5];
    float* out = (float*)d_out;

    k_stats<<<NBH, 256>>>(k, v);
    k_fdft <<<dim3(NBH, 2), 256>>>(q);
    k_mix  <<<128, 512>>>(wre, wim);
    k_local<<<dim3(NBH, 2), 256>>>(q, out);
    k_spec <<<dim3(NBH, 2), 256>>>(out);
}

// round 5
// speedup vs baseline: 1.9006x; 1.9006x over previous
#include <cuda_runtime.h>
#include <cuda_bf16.h>

#define NB 16
#define NL 1024
#define NH 8
#define NE 64
#define NM 64
#define NBH (NB*NH)
#define HE 512
#define SCALE_F 3.814697265625e-06f  // 1/(512*512)

typedef unsigned long long u64;
typedef __nv_bfloat16 bf16;

// -------- scratch (static device globals) --------
static __device__ float g_Mbuf[NBH*NE*NE];                 // [bh][e][o]
static __device__ float g_ksum[NBH*NE];
static __device__ float g_vsum[NBH*NE];
static __device__ float g_X[NBH*128*64];                   // [bh][mr][e]; mr=2m: sum q cos, 2m+1: sum q sin
static __device__ __align__(16) bf16 g_Yt[NBH*64*128];     // [bh][o][mr]: 2m -> f*Yr, 2m+1 -> -f*Yi
static __device__ __align__(16) bf16 g_Tml[128*1024];      // [mr][l]
static __device__ __align__(16) bf16 g_Tlm[1024*128];      // [l][mr]

// ---------------- warp MMA helper (sm_80+ baseline PTX; works on sm_100) ----------------
__device__ __forceinline__ void mma16816(float* d, const unsigned* a, const unsigned* b) {
    asm volatile(
        "mma.sync.aligned.m16n8k16.row.col.f32.bf16.bf16.f32 "
        "{%0,%1,%2,%3}, {%4,%5,%6,%7}, {%8,%9}, {%0,%1,%2,%3};"
        : "+f"(d[0]), "+f"(d[1]), "+f"(d[2]), "+f"(d[3])
        : "r"(a[0]), "r"(a[1]), "r"(a[2]), "r"(a[3]), "r"(b[0]), "r"(b[1]));
}

#define SPA 72   // smem row pitch in bf16 (144B = 4 banks offset/row -> conflict-free frags)

// ===================== twiddle tables =====================
__global__ void __launch_bounds__(256) k_twid() {
    int idx0 = blockIdx.x * 2048 + threadIdx.x;   // 64 blocks cover 131072
    #pragma unroll
    for (int r = 0; r < 8; ++r) {
        int idx = idx0 + r * 256;
        int l = idx >> 7, mr = idx & 127;
        int m = mr >> 1;
        float s, c;
        sincospif((float)((m * l) & 1023) * (1.0f/512.0f), &s, &c);
        float val = (mr & 1) ? s : c;
        bf16 bv = __float2bfloat16(val);
        g_Tlm[l*128 + mr] = bv;
        g_Tml[mr*1024 + l] = bv;
    }
}

// ===================== kernel A: k/v stats (scalar fp32, exact) =====================
__global__ void __launch_bounds__(256) k_stats(const float* __restrict__ kin,
                                               const float* __restrict__ vin) {
    const int bh = blockIdx.x;
    const int b = bh >> 3, h = bh & 7;
    const int t = threadIdx.x;
    __shared__ float sk[8][NE];
    __shared__ float sv[8][NE];
    const int e0 = (t >> 4) << 2;
    const int d0 = (t & 15) << 2;
    float acc[4][4] = {};
    float ka = 0.f, va = 0.f;
    const int base = b * NL * HE + h * NE;
    for (int s0 = 0; s0 < NL; s0 += 8) {
        __syncthreads();
        #pragma unroll
        for (int r = 0; r < 2; ++r) {
            int idx = r * 256 + t;
            int ss = idx >> 6, e = idx & 63;
            int g = base + (s0 + ss) * HE + e;
            sk[ss][e] = kin[g];
            sv[ss][e] = vin[g];
        }
        __syncthreads();
        #pragma unroll
        for (int ss = 0; ss < 8; ++ss) {
            float kr[4], vr[4];
            #pragma unroll
            for (int i = 0; i < 4; ++i) { kr[i] = sk[ss][e0+i]; vr[i] = sv[ss][d0+i]; }
            #pragma unroll
            for (int i = 0; i < 4; ++i)
                #pragma unroll
                for (int j = 0; j < 4; ++j)
                    acc[i][j] = fmaf(kr[i], vr[j], acc[i][j]);
        }
        if (t < 64) {
            #pragma unroll
            for (int ss = 0; ss < 8; ++ss) { ka += sk[ss][t]; va += sv[ss][t]; }
        }
    }
    float* Mo = g_Mbuf + bh * (NE*NE);
    #pragma unroll
    for (int i = 0; i < 4; ++i)
        #pragma unroll
        for (int j = 0; j < 4; ++j)
            Mo[(e0+i)*NE + d0 + j] = acc[i][j];
    if (t < 64) { g_ksum[bh*NE + t] = ka; g_vsum[bh*NE + t] = va; }
}

// ===================== kernel B: forward DFT via warp MMA =====================
// D[mr=128][e=64] = sum_l T_ml[mr,l] * q[l,e]; K=1024 in 16 chunks of 64
__global__ void __launch_bounds__(128) k_fdft_mma(const float* __restrict__ q) {
    __shared__ bf16 sA[128][SPA];   // T chunk  [mr][k]
    __shared__ bf16 sB[64][SPA];    // q^T chunk [e][k]
    const int t = threadIdx.x;
    const int wid = t >> 5, lane = t & 31;
    const int g = lane >> 2, tig = lane & 3;
    const int bh = blockIdx.x;
    const int b = bh >> 3, h = bh & 7;
    const int base = b * NL * HE + h * NE;

    float acc[2][8][4] = {};
    for (int c = 0; c < 16; ++c) {
        __syncthreads();
        // stage A: 128 rows x 64 bf16 (u32 copy)
        #pragma unroll
        for (int it = 0; it < 32; ++it) {
            int idx = it * 128 + t;
            int row = idx >> 5, w = idx & 31;
            ((unsigned*)&sA[row][0])[w] = ((const unsigned*)(g_Tml + row*1024 + c*64))[w];
        }
        // stage B: transpose q -> [e][l], bf16 convert (coalesced over e)
        #pragma unroll
        for (int it = 0; it < 32; ++it) {
            int idx = it * 128 + t;
            int l = idx >> 6, e = idx & 63;
            sB[e][l] = __float2bfloat16(q[base + (c*64 + l)*HE + e]);
        }
        __syncthreads();
        #pragma unroll
        for (int ks = 0; ks < 4; ++ks) {
            const int k0 = ks * 16;
            unsigned bfrag[8][2];
            #pragma unroll
            for (int n = 0; n < 8; ++n) {
                const bf16* bp = &sB[n*8 + g][k0 + tig*2];
                bfrag[n][0] = *(const unsigned*)bp;
                bfrag[n][1] = *(const unsigned*)(bp + 8);
            }
            #pragma unroll
            for (int mt = 0; mt < 2; ++mt) {
                unsigned afrag[4];
                const bf16* ap = &sA[wid*32 + mt*16 + g][k0 + tig*2];
                afrag[0] = *(const unsigned*)ap;
                afrag[1] = *(const unsigned*)(ap + 8*SPA);
                afrag[2] = *(const unsigned*)(ap + 8);
                afrag[3] = *(const unsigned*)(ap + 8*SPA + 8);
                #pragma unroll
                for (int n = 0; n < 8; ++n)
                    mma16816(acc[mt][n], afrag, bfrag[n]);
            }
        }
    }
    // epilogue: D[mr][e] -> g_X
    float* Xb = g_X + bh * 8192;
    #pragma unroll
    for (int mt = 0; mt < 2; ++mt) {
        int m0 = wid*32 + mt*16 + g;
        #pragma unroll
        for (int n = 0; n < 8; ++n) {
            int col = n*8 + tig*2;
            *(float2*)(Xb + m0*64 + col)       = make_float2(acc[mt][n][0], acc[mt][n][1]);
            *(float2*)(Xb + (m0+8)*64 + col)   = make_float2(acc[mt][n][2], acc[mt][n][3]);
        }
    }
}

// ===================== kernel C: per-mode complex mix (scalar fp32) =====================
// Xc = X[2m][e], Xs = X[2m+1][e] (Xi = -Xs)
// Yr = sum_i Xc*Wr + Xs*Wi ; Yi = sum_i Xc*Wi - Xs*Wr
// Yt[o][2m] = f*Yr ; Yt[o][2m+1] = -f*Yi ; f = c_m/2048
__global__ void __launch_bounds__(512) k_mix(const float* __restrict__ wre,
                                             const float* __restrict__ wim) {
    const int h  = blockIdx.x >> 4;
    const int m0 = (blockIdx.x & 15) << 2;
    const int t = threadIdx.x;
    const int b  = t >> 5;
    const int o0 = (t & 31) << 1;
    const int bh = b * NH + h;
    float yr[2][4] = {}, yi[2][4] = {};
    const float* Xb = g_X + bh * 8192;
    for (int i = 0; i < NE; ++i) {
        float xc[4], xs[4];
        #pragma unroll
        for (int mm = 0; mm < 4; ++mm) {
            xc[mm] = Xb[(2*(m0+mm))*64 + i];
            xs[mm] = Xb[(2*(m0+mm)+1)*64 + i];
        }
        #pragma unroll
        for (int oo = 0; oo < 2; ++oo) {
            int wbase = ((h*NE + i)*NE + (o0+oo))*NM + m0;
            float4 wr = *(const float4*)(wre + wbase);
            float4 wi = *(const float4*)(wim + wbase);
            float wrv[4] = {wr.x, wr.y, wr.z, wr.w};
            float wiv[4] = {wi.x, wi.y, wi.z, wi.w};
            #pragma unroll
            for (int mm = 0; mm < 4; ++mm) {
                yr[oo][mm] = fmaf(xc[mm], wrv[mm], yr[oo][mm]);
                yr[oo][mm] = fmaf(xs[mm], wiv[mm], yr[oo][mm]);
                yi[oo][mm] = fmaf(xc[mm], wiv[mm], yi[oo][mm]);
                yi[oo][mm] = fmaf(-xs[mm], wrv[mm], yi[oo][mm]);
            }
        }
    }
    #pragma unroll
    for (int oo = 0; oo < 2; ++oo) {
        bf16* Yo = g_Yt + (bh*64 + o0 + oo) * 128;
        #pragma unroll
        for (int mm = 0; mm < 4; ++mm) {
            int m = m0 + mm;
            float f = (m == 0 ? 1.0f : 2.0f) * (1.0f / 2048.0f);
            Yo[2*m]     = __float2bfloat16(f * yr[oo][mm]);
            Yo[2*m + 1] = __float2bfloat16(-f * yi[oo][mm]);
        }
    }
}

// ===================== kernel D1: linearized local attention (scalar fp32) =====================
__global__ void __launch_bounds__(256) k_local(const float* __restrict__ q,
                                               float* __restrict__ out) {
    const int bh = blockIdx.x;
    const int b = bh >> 3, h = bh & 7;
    const int t = threadIdx.x;
    __shared__ float sM[NE*NE];
    __shared__ float sq[64][NE];
    __shared__ float sks[NE];
    __shared__ float svs[NE];
    const float* Mi = g_Mbuf + bh*(NE*NE);
    for (int idx = t; idx < NE*NE; idx += 256) sM[idx] = Mi[idx];
    if (t < NE) { sks[t] = g_ksum[bh*NE+t]; svs[t] = g_vsum[bh*NE+t]; }
    const int og = t & 15, lg = t >> 4;
    const int o0 = og << 2;
    const int base  = b * NL * HE + h * NE;
    const int lbase = blockIdx.y * 512;
    for (int l0 = lbase; l0 < lbase + 512; l0 += 64) {
        __syncthreads();
        const float4* qg = (const float4*)(q + base + l0*HE);
        #pragma unroll
        for (int r = 0; r < 4; ++r) {
            int f = r*256 + t;
            int row = f >> 4, c4 = f & 15;
            ((float4*)sq)[row*16+c4] = qg[row*128 + c4];
        }
        __syncthreads();
        float acc[4][4] = {};
        float z[4] = {};
        #pragma unroll 4
        for (int e = 0; e < NE; ++e) {
            float ks = sks[e];
            float4 mv = *(const float4*)&sM[e*NE + o0];
            #pragma unroll
            for (int ll = 0; ll < 4; ++ll) {
                float qv = sq[lg*4+ll][e];
                z[ll]      = fmaf(qv, ks,   z[ll]);
                acc[ll][0] = fmaf(qv, mv.x, acc[ll][0]);
                acc[ll][1] = fmaf(qv, mv.y, acc[ll][1]);
                acc[ll][2] = fmaf(qv, mv.z, acc[ll][2]);
                acc[ll][3] = fmaf(qv, mv.w, acc[ll][3]);
            }
        }
        #pragma unroll
        for (int ll = 0; ll < 4; ++ll) {
            int l = l0 + lg*4 + ll;
            float Z = 1024.0f + SCALE_F * z[ll];
            float inv = 0.5f / Z;
            float4 ov;
            ov.x = (svs[o0+0] + SCALE_F*acc[ll][0]) * inv;
            ov.y = (svs[o0+1] + SCALE_F*acc[ll][1]) * inv;
            ov.z = (svs[o0+2] + SCALE_F*acc[ll][2]) * inv;
            ov.w = (svs[o0+3] + SCALE_F*acc[ll][3]) * inv;
            *(float4*)(out + (b*NL + l)*HE + h*NE + o0) = ov;
        }
    }
}

// ===================== kernel D2: inverse DFT via warp MMA, RMW into out =====================
// D[l=128][o=64] = sum_mr T_lm[l,mr] * Yt[o,mr]; K=128 in 2 chunks of 64
__global__ void __launch_bounds__(128) k_spec_mma(float* __restrict__ out) {
    __shared__ bf16 sA[128][SPA];   // T_lm tile [l][k]
    __shared__ bf16 sB[64][SPA];    // Yt tile   [o][k]
    const int t = threadIdx.x;
    const int wid = t >> 5, lane = t & 31;
    const int g = lane >> 2, tig = lane & 3;
    const int bh = blockIdx.x;
    const int b = bh >> 3, h = bh & 7;
    const int l0 = blockIdx.y * 128;
    const bf16* Yb = g_Yt + bh * 8192;

    float acc[2][8][4] = {};
    for (int c = 0; c < 2; ++c) {
        __syncthreads();
        #pragma unroll
        for (int it = 0; it < 32; ++it) {
            int idx = it * 128 + t;
            int row = idx >> 5, w = idx & 31;
            ((unsigned*)&sA[row][0])[w] = ((const unsigned*)(g_Tlm + (l0 + row)*128 + c*64))[w];
        }
        #pragma unroll
        for (int it = 0; it < 16; ++it) {
            int idx = it * 128 + t;
            int row = idx >> 5, w = idx & 31;
            ((unsigned*)&sB[row][0])[w] = ((const unsigned*)(Yb + row*128 + c*64))[w];
        }
        __syncthreads();
        #pragma unroll
        for (int ks = 0; ks < 4; ++ks) {
            const int k0 = ks * 16;
            unsigned bfrag[8][2];
            #pragma unroll
            for (int n = 0; n < 8; ++n) {
                const bf16* bp = &sB[n*8 + g][k0 + tig*2];
                bfrag[n][0] = *(const unsigned*)bp;
                bfrag[n][1] = *(const unsigned*)(bp + 8);
            }
            #pragma unroll
            for (int mt = 0; mt < 2; ++mt) {
                unsigned afrag[4];
                const bf16* ap = &sA[wid*32 + mt*16 + g][k0 + tig*2];
                afrag[0] = *(const unsigned*)ap;
                afrag[1] = *(const unsigned*)(ap + 8*SPA);
                afrag[2] = *(const unsigned*)(ap + 8);
                afrag[3] = *(const unsigned*)(ap + 8*SPA + 8);
                #pragma unroll
                for (int n = 0; n < 8; ++n)
                    mma16816(acc[mt][n], afrag, bfrag[n]);
            }
        }
    }
    // epilogue: out[(b,l),(h,o)] += D
    #pragma unroll
    for (int mt = 0; mt < 2; ++mt) {
        int m0 = wid*32 + mt*16 + g;
        #pragma unroll
        for (int n = 0; n < 8; ++n) {
            int col = n*8 + tig*2;
            float* p0 = out + (b*NL + l0 + m0)*HE + h*NE + col;
            float2 c0 = *(const float2*)p0;
            c0.x += acc[mt][n][0]; c0.y += acc[mt][n][1];
            *(float2*)p0 = c0;
            float* p1 = out + (b*NL + l0 + m0 + 8)*HE + h*NE + col;
            float2 c1 = *(const float2*)p1;
            c1.x += acc[mt][n][2]; c1.y += acc[mt][n][3];
            *(float2*)p1 = c1;
        }
    }
}

// ===================== launch =====================
extern "C" void kernel_launch(void* const* d_in, const int* in_sizes, int n_in,
                              void* d_out, int out_size) {
    (void)in_sizes; (void)n_in; (void)out_size;
    const float* q   = (const float*)d_in[0];
    const float* k   = (const float*)d_in[1];
    const float* v   = (const float*)d_in[2];
    // d_in[3] = mask (present -> reference applies no masking); unused
    const float* wre = (const float*)d_in[4];
    const float* wim = (const float*)d_in[5];
    float* out = (float*)d_out;

    k_twid    <<<64, 256>>>();
    k_stats   <<<NBH, 256>>>(k, v);
    k_fdft_mma<<<NBH, 128>>>(q);
    k_mix     <<<128, 512>>>(wre, wim);
    k_local   <<<dim3(NBH, 2), 256>>>(q, out);
    k_spec_mma<<<dim3(NBH, 8), 128>>>(out);
}

// round 6
// speedup vs baseline: 2.0663x; 1.0872x over previous
#include <cuda_runtime.h>
#include <cuda_bf16.h>

#define NB 16
#define NL 1024
#define NH 8
#define NE 64
#define NM 64
#define NBH (NB*NH)
#define HE 512
#define SCALE_F 3.814697265625e-06f  // 1/(512*512)

typedef unsigned long long u64;
typedef unsigned u32;
typedef __nv_bfloat16 bf16;

// -------- scratch (static device globals) --------
static __device__ float g_Mbuf[NBH*NE*NE];                 // [bh][e][o] fp32
static __device__ float g_ksum[NBH*NE];
static __device__ float g_vsum[NBH*NE];
static __device__ float g_X[NBH*128*64];                   // [bh][mr][e]; mr=2m: sum q cos, 2m+1: sum q sin
static __device__ __align__(16) bf16 g_Yt[NBH*64*128];     // [bh][o][mr]: 2m -> f*Yr, 2m+1 -> -f*Yi
static __device__ __align__(16) bf16 g_Tml[128*1024];      // [mr][l]
static __device__ __align__(16) bf16 g_Tlm[1024*128];      // [l][mr]
static __device__ u32 g_WtR[NH*64*64*64];                  // [h][m][i][o] u32=(bf16 Wr, bf16 Wi)
static __device__ u32 g_WtI[NH*64*64*64];                  // [h][m][i][o] u32=(bf16 Wi, bf16 -Wr)

// ---------------- warp MMA helper (sm_80+ baseline PTX) ----------------
__device__ __forceinline__ void mma16816(float* d, const u32* a, const u32* b) {
    asm volatile(
        "mma.sync.aligned.m16n8k16.row.col.f32.bf16.bf16.f32 "
        "{%0,%1,%2,%3}, {%4,%5,%6,%7}, {%8,%9}, {%0,%1,%2,%3};"
        : "+f"(d[0]), "+f"(d[1]), "+f"(d[2]), "+f"(d[3])
        : "r"(a[0]), "r"(a[1]), "r"(a[2]), "r"(a[3]), "r"(b[0]), "r"(b[1]));
}
__device__ __forceinline__ u32 pkbf(float a, float b) {
    __nv_bfloat162 p = __floats2bfloat162_rn(a, b);   // a -> low
    return *(u32*)&p;
}

#define SPA 72    // bf16 pitch for K<=64 tiles
#define SPB 130   // bf16 pitch for K=128 tiles (65 u32 -> conflict-free u32 rows)

// ===================== twiddle tables =====================
__global__ void __launch_bounds__(256) k_twid() {
    int idx0 = blockIdx.x * 2048 + threadIdx.x;
    #pragma unroll
    for (int r = 0; r < 8; ++r) {
        int idx = idx0 + r * 256;
        int l = idx >> 7, mr = idx & 127;
        int m = mr >> 1;
        float s, c;
        sincospif((float)((m * l) & 1023) * (1.0f/512.0f), &s, &c);
        bf16 bv = __float2bfloat16((mr & 1) ? s : c);
        g_Tlm[l*128 + mr] = bv;
        g_Tml[mr*1024 + l] = bv;
    }
}

// ===================== weight transpose: W[h,i,o,m] -> WtR/WtI[h][m][i][o] =====================
__global__ void __launch_bounds__(256) k_wt(const float* __restrict__ wre,
                                            const float* __restrict__ wim) {
    __shared__ float smr[64][65];
    __shared__ float smi[64][65];
    const int hi = blockIdx.x;             // h*64 + i
    const int h = hi >> 6, i = hi & 63;
    const int t = threadIdx.x;
    const float* pr = wre + (size_t)hi * 4096;   // [o][m]
    const float* pq = wim + (size_t)hi * 4096;
    #pragma unroll
    for (int it = 0; it < 4; ++it) {
        int idx = it * 256 + t;
        int o = idx >> 4, m4 = idx & 15;
        float4 vr = *(const float4*)(pr + o*64 + m4*4);
        float4 vi = *(const float4*)(pq + o*64 + m4*4);
        smr[o][m4*4+0] = vr.x; smr[o][m4*4+1] = vr.y; smr[o][m4*4+2] = vr.z; smr[o][m4*4+3] = vr.w;
        smi[o][m4*4+0] = vi.x; smi[o][m4*4+1] = vi.y; smi[o][m4*4+2] = vi.z; smi[o][m4*4+3] = vi.w;
    }
    __syncthreads();
    #pragma unroll
    for (int it = 0; it < 16; ++it) {
        int idx = it * 256 + t;
        int m = idx >> 6, o = idx & 63;
        float wr = smr[o][m], wi = smi[o][m];
        int dst = ((h*64 + m)*64 + i)*64 + o;
        g_WtR[dst] = pkbf(wr, wi);
        g_WtI[dst] = pkbf(wi, -wr);
    }
}

// ===================== kernel A: M = k^T v via MMA; exact fp32 ksum/vsum =====================
__global__ void __launch_bounds__(128) k_stats_mma(const float* __restrict__ kin,
                                                   const float* __restrict__ vin) {
    __shared__ bf16 sK[64][SPA];
    __shared__ bf16 sV[64][SPA];
    __shared__ float red[128];
    const int bh = blockIdx.x;
    const int b = bh >> 3, h = bh & 7;
    const int t = threadIdx.x;
    const int wid = t >> 5, lane = t & 31, g = lane >> 2, tig = lane & 3;
    const int base = b * NL * HE + h * NE;
    float ka = 0.f, va = 0.f;
    float acc[8][4] = {};
    for (int c = 0; c < 16; ++c) {
        __syncthreads();
        #pragma unroll
        for (int it = 0; it < 32; ++it) {
            int idx = it * 128 + t;
            int s = idx >> 6, e = idx & 63;
            float kv = kin[base + (c*64 + s)*HE + e];
            float vv = vin[base + (c*64 + s)*HE + e];
            sK[e][s] = __float2bfloat16(kv);
            sV[e][s] = __float2bfloat16(vv);
            ka += kv; va += vv;
        }
        __syncthreads();
        #pragma unroll
        for (int ks = 0; ks < 4; ++ks) {
            const int k0 = ks * 16;
            u32 afrag[4];
            const bf16* ap = &sK[wid*16 + g][k0 + tig*2];
            afrag[0] = *(const u32*)ap;
            afrag[1] = *(const u32*)(ap + 8*SPA);
            afrag[2] = *(const u32*)(ap + 8);
            afrag[3] = *(const u32*)(ap + 8*SPA + 8);
            #pragma unroll
            for (int n = 0; n < 8; ++n) {
                const bf16* bp = &sV[n*8 + g][k0 + tig*2];
                u32 bfr[2] = {*(const u32*)bp, *(const u32*)(bp + 8)};
                mma16816(acc[n], afrag, bfr);
            }
        }
    }
    float* Mo = g_Mbuf + bh * 4096;
    const int e0 = wid*16 + g;
    #pragma unroll
    for (int n = 0; n < 8; ++n) {
        int col = n*8 + tig*2;
        *(float2*)(Mo + e0*64 + col)     = make_float2(acc[n][0], acc[n][1]);
        *(float2*)(Mo + (e0+8)*64 + col) = make_float2(acc[n][2], acc[n][3]);
    }
    red[t] = ka; __syncthreads();
    if (t < 64) g_ksum[bh*64 + t] = red[t] + red[t+64];
    __syncthreads();
    red[t] = va; __syncthreads();
    if (t < 64) g_vsum[bh*64 + t] = red[t] + red[t+64];
}

// ===================== kernel B: forward DFT via warp MMA (unchanged) =====================
__global__ void __launch_bounds__(128) k_fdft_mma(const float* __restrict__ q) {
    __shared__ bf16 sA[128][SPA];
    __shared__ bf16 sB[64][SPA];
    const int t = threadIdx.x;
    const int wid = t >> 5, lane = t & 31;
    const int g = lane >> 2, tig = lane & 3;
    const int bh = blockIdx.x;
    const int b = bh >> 3, h = bh & 7;
    const int base = b * NL * HE + h * NE;

    float acc[2][8][4] = {};
    for (int c = 0; c < 16; ++c) {
        __syncthreads();
        #pragma unroll
        for (int it = 0; it < 32; ++it) {
            int idx = it * 128 + t;
            int row = idx >> 5, w = idx & 31;
            ((u32*)&sA[row][0])[w] = ((const u32*)(g_Tml + row*1024 + c*64))[w];
        }
        #pragma unroll
        for (int it = 0; it < 32; ++it) {
            int idx = it * 128 + t;
            int l = idx >> 6, e = idx & 63;
            sB[e][l] = __float2bfloat16(q[base + (c*64 + l)*HE + e]);
        }
        __syncthreads();
        #pragma unroll
        for (int ks = 0; ks < 4; ++ks) {
            const int k0 = ks * 16;
            u32 bfrag[8][2];
            #pragma unroll
            for (int n = 0; n < 8; ++n) {
                const bf16* bp = &sB[n*8 + g][k0 + tig*2];
                bfrag[n][0] = *(const u32*)bp;
                bfrag[n][1] = *(const u32*)(bp + 8);
            }
            #pragma unroll
            for (int mt = 0; mt < 2; ++mt) {
                u32 afrag[4];
                const bf16* ap = &sA[wid*32 + mt*16 + g][k0 + tig*2];
                afrag[0] = *(const u32*)ap;
                afrag[1] = *(const u32*)(ap + 8*SPA);
                afrag[2] = *(const u32*)(ap + 8);
                afrag[3] = *(const u32*)(ap + 8*SPA + 8);
                #pragma unroll
                for (int n = 0; n < 8; ++n)
                    mma16816(acc[mt][n], afrag, bfrag[n]);
            }
        }
    }
    float* Xb = g_X + bh * 8192;
    #pragma unroll
    for (int mt = 0; mt < 2; ++mt) {
        int m0 = wid*32 + mt*16 + g;
        #pragma unroll
        for (int n = 0; n < 8; ++n) {
            int col = n*8 + tig*2;
            *(float2*)(Xb + m0*64 + col)     = make_float2(acc[mt][n][0], acc[mt][n][1]);
            *(float2*)(Xb + (m0+8)*64 + col) = make_float2(acc[mt][n][2], acc[mt][n][3]);
        }
    }
}

// ===================== kernel C: complex mix via MMA =====================
// per (h,m): Y[16b x 64o], A[b][k]=(Xc,Xs interleaved), Br/Bi from WtR/WtI
__global__ void __launch_bounds__(128) k_mix_mma() {
    __shared__ bf16 sA[16][SPB];
    __shared__ bf16 sBr[64][SPB];
    __shared__ bf16 sBi[64][SPB];
    const int bx = blockIdx.x;
    const int h = bx >> 6, m = bx & 63;
    const int t = threadIdx.x;
    const int wid = t >> 5, lane = t & 31, g = lane >> 2, tig = lane & 3;
    // stage A: 16 b x 64 i pairs
    #pragma unroll
    for (int it = 0; it < 8; ++it) {
        int idx = it * 128 + t;
        int b = idx >> 6, i = idx & 63;
        const float* Xb = g_X + (b*8 + h)*8192 + (2*m)*64;
        *(u32*)&sA[b][2*i] = pkbf(Xb[i], Xb[64 + i]);
    }
    // stage B
    const u32* WR = g_WtR + (h*64 + m)*4096;
    const u32* WI = g_WtI + (h*64 + m)*4096;
    #pragma unroll
    for (int it = 0; it < 32; ++it) {
        int idx = it * 128 + t;
        int i = idx >> 6, o = idx & 63;
        *(u32*)&sBr[o][2*i] = WR[i*64 + o];
        *(u32*)&sBi[o][2*i] = WI[i*64 + o];
    }
    __syncthreads();
    float acc[2][2][4] = {};   // [part][nfrag][4]
    #pragma unroll
    for (int ks = 0; ks < 8; ++ks) {
        const int k0 = ks * 16;
        u32 afrag[4];
        const bf16* ap = &sA[g][k0 + tig*2];
        afrag[0] = *(const u32*)ap;
        afrag[1] = *(const u32*)(ap + 8*SPB);
        afrag[2] = *(const u32*)(ap + 8);
        afrag[3] = *(const u32*)(ap + 8*SPB + 8);
        #pragma unroll
        for (int n = 0; n < 2; ++n) {
            int o = wid*16 + n*8 + g;
            const bf16* brp = &sBr[o][k0 + tig*2];
            u32 br[2] = {*(const u32*)brp, *(const u32*)(brp + 8)};
            mma16816(acc[0][n], afrag, br);
            const bf16* bip = &sBi[o][k0 + tig*2];
            u32 bi2[2] = {*(const u32*)bip, *(const u32*)(bip + 8)};
            mma16816(acc[1][n], afrag, bi2);
        }
    }
    const float f = (m == 0 ? 1.0f : 2.0f) * (1.0f / 2048.0f);
    u32* Yt32 = (u32*)g_Yt;
    #pragma unroll
    for (int n = 0; n < 2; ++n)
        #pragma unroll
        for (int cc = 0; cc < 2; ++cc) {
            int o = wid*16 + n*8 + tig*2 + cc;
            Yt32[((g*8 + h)*64 + o)*64 + m]     = pkbf(f*acc[0][n][cc],   -f*acc[1][n][cc]);
            Yt32[(((g+8)*8 + h)*64 + o)*64 + m] = pkbf(f*acc[0][n][cc+2], -f*acc[1][n][cc+2]);
        }
}

// ===================== kernel D1: local attention via MMA (ksum folded as col 64) =====================
__global__ void __launch_bounds__(128) k_local_mma(const float* __restrict__ q,
                                                   float* __restrict__ out) {
    __shared__ bf16 sQ[128][SPA];
    __shared__ bf16 sMt[72][SPA];   // rows: o=0..63 -> M^T, 64 -> ksum, 65..71 -> 0
    __shared__ float svs[64];
    const int bh = blockIdx.x;
    const int b = bh >> 3, h = bh & 7;
    const int l0 = blockIdx.y * 128;
    const int t = threadIdx.x;
    const int wid = t >> 5, lane = t & 31, g = lane >> 2, tig = lane & 3;
    const int base = b * NL * HE + h * NE;
    const float* Mi = g_Mbuf + bh * 4096;
    #pragma unroll
    for (int it = 0; it < 32; ++it) {
        int idx = it * 128 + t;
        int e = idx >> 6, o = idx & 63;
        sMt[o][e] = __float2bfloat16(Mi[e*64 + o]);
    }
    if (t < 64) {
        sMt[64][t] = __float2bfloat16(g_ksum[bh*64 + t]);
        svs[t] = g_vsum[bh*64 + t];
    }
    for (int idx = t; idx < 7*SPA; idx += 128)
        sMt[65 + idx/SPA][idx % SPA] = __float2bfloat16(0.f);
    #pragma unroll
    for (int it = 0; it < 64; ++it) {
        int idx = it * 128 + t;
        int l = idx >> 6, e = idx & 63;
        sQ[l][e] = __float2bfloat16(q[base + (l0 + l)*HE + e]);
    }
    __syncthreads();
    float acc[2][9][4] = {};
    #pragma unroll
    for (int ks = 0; ks < 4; ++ks) {
        const int k0 = ks * 16;
        #pragma unroll
        for (int mt = 0; mt < 2; ++mt) {
            u32 afrag[4];
            const bf16* ap = &sQ[wid*32 + mt*16 + g][k0 + tig*2];
            afrag[0] = *(const u32*)ap;
            afrag[1] = *(const u32*)(ap + 8*SPA);
            afrag[2] = *(const u32*)(ap + 8);
            afrag[3] = *(const u32*)(ap + 8*SPA + 8);
            #pragma unroll
            for (int n = 0; n < 9; ++n) {
                const bf16* bp = &sMt[n*8 + g][k0 + tig*2];
                u32 bfr[2] = {*(const u32*)bp, *(const u32*)(bp + 8)};
                mma16816(acc[mt][n], afrag, bfr);
            }
        }
    }
    #pragma unroll
    for (int mt = 0; mt < 2; ++mt) {
        const int r0 = wid*32 + mt*16 + g;
        float z0 = __shfl_sync(0xffffffffu, acc[mt][8][0], lane & ~3);
        float z1 = __shfl_sync(0xffffffffu, acc[mt][8][2], lane & ~3);
        float inv0 = 0.5f / (1024.0f + SCALE_F * z0);
        float inv1 = 0.5f / (1024.0f + SCALE_F * z1);
        #pragma unroll
        for (int n = 0; n < 8; ++n) {
            int col = n*8 + tig*2;
            float2 o0 = make_float2((svs[col]   + SCALE_F*acc[mt][n][0]) * inv0,
                                    (svs[col+1] + SCALE_F*acc[mt][n][1]) * inv0);
            *(float2*)(out + (b*NL + l0 + r0)*HE + h*64 + col) = o0;
            float2 o1 = make_float2((svs[col]   + SCALE_F*acc[mt][n][2]) * inv1,
                                    (svs[col+1] + SCALE_F*acc[mt][n][3]) * inv1);
            *(float2*)(out + (b*NL + l0 + r0 + 8)*HE + h*64 + col) = o1;
        }
    }
}

// ===================== kernel D2: inverse DFT via warp MMA, RMW into out (unchanged) =====================
__global__ void __launch_bounds__(128) k_spec_mma(float* __restrict__ out) {
    __shared__ bf16 sA[128][SPA];
    __shared__ bf16 sB[64][SPA];
    const int t = threadIdx.x;
    const int wid = t >> 5, lane = t & 31;
    const int g = lane >> 2, tig = lane & 3;
    const int bh = blockIdx.x;
    const int b = bh >> 3, h = bh & 7;
    const int l0 = blockIdx.y * 128;
    const bf16* Yb = g_Yt + bh * 8192;

    float acc[2][8][4] = {};
    for (int c = 0; c < 2; ++c) {
        __syncthreads();
        #pragma unroll
        for (int it = 0; it < 32; ++it) {
            int idx = it * 128 + t;
            int row = idx >> 5, w = idx & 31;
            ((u32*)&sA[row][0])[w] = ((const u32*)(g_Tlm + (l0 + row)*128 + c*64))[w];
        }
        #pragma unroll
        for (int it = 0; it < 16; ++it) {
            int idx = it * 128 + t;
            int row = idx >> 5, w = idx & 31;
            ((u32*)&sB[row][0])[w] = ((const u32*)(Yb + row*128 + c*64))[w];
        }
        __syncthreads();
        #pragma unroll
        for (int ks = 0; ks < 4; ++ks) {
            const int k0 = ks * 16;
            u32 bfrag[8][2];
            #pragma unroll
            for (int n = 0; n < 8; ++n) {
                const bf16* bp = &sB[n*8 + g][k0 + tig*2];
                bfrag[n][0] = *(const u32*)bp;
                bfrag[n][1] = *(const u32*)(bp + 8);
            }
            #pragma unroll
            for (int mt = 0; mt < 2; ++mt) {
                u32 afrag[4];
                const bf16* ap = &sA[wid*32 + mt*16 + g][k0 + tig*2];
                afrag[0] = *(const u32*)ap;
                afrag[1] = *(const u32*)(ap + 8*SPA);
                afrag[2] = *(const u32*)(ap + 8);
                afrag[3] = *(const u32*)(ap + 8*SPA + 8);
                #pragma unroll
                for (int n = 0; n < 8; ++n)
                    mma16816(acc[mt][n], afrag, bfrag[n]);
            }
        }
    }
    #pragma unroll
    for (int mt = 0; mt < 2; ++mt) {
        int m0 = wid*32 + mt*16 + g;
        #pragma unroll
        for (int n = 0; n < 8; ++n) {
            int col = n*8 + tig*2;
            float* p0 = out + (b*NL + l0 + m0)*HE + h*NE + col;
            float2 c0 = *(const float2*)p0;
            c0.x += acc[mt][n][0]; c0.y += acc[mt][n][1];
            *(float2*)p0 = c0;
            float* p1 = out + (b*NL + l0 + m0 + 8)*HE + h*NE + col;
            float2 c1 = *(const float2*)p1;
            c1.x += acc[mt][n][2]; c1.y += acc[mt][n][3];
            *(float2*)p1 = c1;
        }
    }
}

// ===================== launch =====================
extern "C" void kernel_launch(void* const* d_in, const int* in_sizes, int n_in,
                              void* d_out, int out_size) {
    (void)in_sizes; (void)n_in; (void)out_size;
    const float* q   = (const float*)d_in[0];
    const float* k   = (const float*)d_in[1];
    const float* v   = (const float*)d_in[2];
    // d_in[3] = mask (present -> reference applies no masking); unused
    const float* wre = (const float*)d_in[4];
    const float* wim = (const float*)d_in[5];
    float* out = (float*)d_out;

    k_twid     <<<64, 256>>>();
    k_wt       <<<512, 256>>>(wre, wim);
    k_stats_mma<<<NBH, 128>>>(k, v);
    k_fdft_mma <<<NBH, 128>>>(q);
    k_mix_mma  <<<512, 128>>>();
    k_local_mma<<<dim3(NBH, 8), 128>>>(q, out);
    k_spec_mma <<<dim3(NBH, 8), 128>>>(out);
}

// round 7
// speedup vs baseline: 4.2802x; 2.0715x over previous
#include <cuda_runtime.h>
#include <cuda_bf16.h>

#define NB 16
#define NL 1024
#define NH 8
#define NE 64
#define NM 64
#define NBH (NB*NH)
#define HE 512
#define SCALE_F 3.814697265625e-06f  // 1/(512*512)

typedef unsigned long long u64;
typedef unsigned u32;
typedef __nv_bfloat16 bf16;

// -------- scratch (static device globals) --------
static __device__ float g_Mt[2*NBH*NE*NE];                 // K-split partials of M^T: [bh*2+ky][o][e]
static __device__ float g_ksp[2*NBH*NE];
static __device__ float g_vsp[2*NBH*NE];
static __device__ float g_X[2*NBH*128*64];                 // K-split partials: [bh*2+ky][mr][e]
static __device__ __align__(16) bf16 g_Yt[NBH*64*128];     // [bh][o][mr]: 2m -> f*Yr, 2m+1 -> -f*Yi
static __device__ __align__(16) bf16 g_Tml[128*1024];      // [mr][l]
static __device__ __align__(16) bf16 g_Tlm[1024*128];      // [l][mr]
static __device__ u32 g_WtR[NH*64*64*64];                  // [h][m][i][o] u32=(bf16 Wr, bf16 Wi)
static __device__ u32 g_WtI[NH*64*64*64];                  // [h][m][i][o] u32=(bf16 Wi, bf16 -Wr)

// ---------------- warp MMA helper ----------------
__device__ __forceinline__ void mma16816(float* d, const u32* a, const u32* b) {
    asm volatile(
        "mma.sync.aligned.m16n8k16.row.col.f32.bf16.bf16.f32 "
        "{%0,%1,%2,%3}, {%4,%5,%6,%7}, {%8,%9}, {%0,%1,%2,%3};"
        : "+f"(d[0]), "+f"(d[1]), "+f"(d[2]), "+f"(d[3])
        : "r"(a[0]), "r"(a[1]), "r"(a[2]), "r"(a[3]), "r"(b[0]), "r"(b[1]));
}
__device__ __forceinline__ u32 pkbf(float a, float b) {
    __nv_bfloat162 p = __floats2bfloat162_rn(a, b);   // a -> low
    return *(u32*)&p;
}

#define SPA 72    // bf16 pitch, K<=64 tiles: frag bank = 4g+tig -> conflict-free
#define SPB 136   // bf16 pitch, K=128 tiles: 68 u32/row -> frag bank = 4g+tig -> conflict-free

// ===================== twiddle tables =====================
__global__ void __launch_bounds__(256) k_twid() {
    int idx0 = blockIdx.x * 2048 + threadIdx.x;
    #pragma unroll
    for (int r = 0; r < 8; ++r) {
        int idx = idx0 + r * 256;
        int l = idx >> 7, mr = idx & 127;
        int m = mr >> 1;
        float s, c;
        sincospif((float)((m * l) & 1023) * (1.0f/512.0f), &s, &c);
        bf16 bv = __float2bfloat16((mr & 1) ? s : c);
        g_Tlm[l*128 + mr] = bv;
        g_Tml[mr*1024 + l] = bv;
    }
}

// ===================== weight transpose: W[h,i,o,m] -> WtR/WtI[h][m][i][o] =====================
__global__ void __launch_bounds__(256) k_wt(const float* __restrict__ wre,
                                            const float* __restrict__ wim) {
    __shared__ float smr[64][65];
    __shared__ float smi[64][65];
    const int hi = blockIdx.x;             // h*64 + i
    const int h = hi >> 6, i = hi & 63;
    const int t = threadIdx.x;
    const float* pr = wre + (size_t)hi * 4096;   // [o][m]
    const float* pq = wim + (size_t)hi * 4096;
    #pragma unroll
    for (int it = 0; it < 4; ++it) {
        int idx = it * 256 + t;
        int o = idx >> 4, m4 = idx & 15;
        float4 vr = *(const float4*)(pr + o*64 + m4*4);
        float4 vi = *(const float4*)(pq + o*64 + m4*4);
        smr[o][m4*4+0] = vr.x; smr[o][m4*4+1] = vr.y; smr[o][m4*4+2] = vr.z; smr[o][m4*4+3] = vr.w;
        smi[o][m4*4+0] = vi.x; smi[o][m4*4+1] = vi.y; smi[o][m4*4+2] = vi.z; smi[o][m4*4+3] = vi.w;
    }
    __syncthreads();
    #pragma unroll
    for (int it = 0; it < 16; ++it) {
        int idx = it * 256 + t;
        int m = idx >> 6, o = idx & 63;
        float wr = smr[o][m], wi = smi[o][m];
        int dst = ((h*64 + m)*64 + i)*64 + o;
        g_WtR[dst] = pkbf(wr, wi);
        g_WtI[dst] = pkbf(wi, -wr);
    }
}

// ===================== kernel A: M^T = v^T k via MMA, K-split x2; exact fp32 ksum/vsum =====================
__global__ void __launch_bounds__(256) k_stats_mma(const float* __restrict__ kin,
                                                   const float* __restrict__ vin) {
    __shared__ bf16 sV[64][SPA];   // A: rows o, k = s
    __shared__ bf16 sK[64][SPA];   // B: rows e, k = s
    __shared__ float red[256];
    const int bh = blockIdx.x, ky = blockIdx.y;
    const int b = bh >> 3, h = bh & 7;
    const int t = threadIdx.x;
    const int wid = t >> 5, lane = t & 31, g = lane >> 2, tig = lane & 3;
    const int ot = wid >> 1, eh = wid & 1;
    const int base = b * NL * HE + h * NE + ky * 512 * HE;
    float ka = 0.f, va = 0.f;
    float acc[4][4] = {};
    for (int c = 0; c < 8; ++c) {
        __syncthreads();
        #pragma unroll
        for (int it = 0; it < 16; ++it) {
            int idx = it * 256 + t;
            int s = idx >> 6, o = idx & 63;
            float vv = vin[base + (c*64 + s)*HE + o];
            float kv = kin[base + (c*64 + s)*HE + o];
            sV[o][s] = __float2bfloat16(vv);
            sK[o][s] = __float2bfloat16(kv);
            ka += kv; va += vv;
        }
        __syncthreads();
        #pragma unroll
        for (int ks = 0; ks < 4; ++ks) {
            const int k0 = ks * 16;
            u32 a[4];
            const bf16* ap = &sV[ot*16 + g][k0 + tig*2];
            a[0] = *(const u32*)ap;
            a[1] = *(const u32*)(ap + 8*SPA);
            a[2] = *(const u32*)(ap + 8);
            a[3] = *(const u32*)(ap + 8*SPA + 8);
            #pragma unroll
            for (int n = 0; n < 4; ++n) {
                const bf16* bp = &sK[eh*32 + n*8 + g][k0 + tig*2];
                u32 bfr[2] = {*(const u32*)bp, *(const u32*)(bp + 8)};
                mma16816(acc[n], a, bfr);
            }
        }
    }
    float* Mo = g_Mt + (bh*2 + ky) * 4096;
    const int o0 = ot*16 + g;
    #pragma unroll
    for (int n = 0; n < 4; ++n) {
        int col = eh*32 + n*8 + tig*2;
        *(float2*)(Mo + o0*64 + col)     = make_float2(acc[n][0], acc[n][1]);
        *(float2*)(Mo + (o0+8)*64 + col) = make_float2(acc[n][2], acc[n][3]);
    }
    red[t] = ka; __syncthreads();
    if (t < 64) g_ksp[(bh*2+ky)*64 + t] = red[t] + red[t+64] + red[t+128] + red[t+192];
    __syncthreads();
    red[t] = va; __syncthreads();
    if (t < 64) g_vsp[(bh*2+ky)*64 + t] = red[t] + red[t+64] + red[t+128] + red[t+192];
}

// ===================== kernel B: forward DFT via warp MMA, K-split x2, 8 warps =====================
__global__ void __launch_bounds__(256) k_fdft_mma(const float* __restrict__ q) {
    __shared__ bf16 sA[128][SPA];   // T rows mr
    __shared__ bf16 sB[64][SPA];    // q^T rows e
    const int bh = blockIdx.x, ky = blockIdx.y;
    const int b = bh >> 3, h = bh & 7;
    const int t = threadIdx.x;
    const int wid = t >> 5, lane = t & 31, g = lane >> 2, tig = lane & 3;
    const int base = b * NL * HE + h * NE;

    float acc[8][4] = {};
    for (int c = 0; c < 8; ++c) {
        const int cc = ky*8 + c;
        __syncthreads();
        #pragma unroll
        for (int it = 0; it < 16; ++it) {
            int idx = it * 256 + t;
            int row = idx >> 5, w = idx & 31;
            ((u32*)&sA[row][0])[w] = ((const u32*)(g_Tml + row*1024 + cc*64))[w];
        }
        #pragma unroll
        for (int it = 0; it < 16; ++it) {
            int idx = it * 256 + t;
            int l = idx >> 6, e = idx & 63;
            sB[e][l] = __float2bfloat16(q[base + (cc*64 + l)*HE + e]);
        }
        __syncthreads();
        #pragma unroll
        for (int ks = 0; ks < 4; ++ks) {
            const int k0 = ks * 16;
            u32 a[4];
            const bf16* ap = &sA[wid*16 + g][k0 + tig*2];
            a[0] = *(const u32*)ap;
            a[1] = *(const u32*)(ap + 8*SPA);
            a[2] = *(const u32*)(ap + 8);
            a[3] = *(const u32*)(ap + 8*SPA + 8);
            #pragma unroll
            for (int n = 0; n < 8; ++n) {
                const bf16* bp = &sB[n*8 + g][k0 + tig*2];
                u32 bfr[2] = {*(const u32*)bp, *(const u32*)(bp + 8)};
                mma16816(acc[n], a, bfr);
            }
        }
    }
    float* Xb = g_X + (bh*2 + ky) * 8192;
    const int m0 = wid*16 + g;
    #pragma unroll
    for (int n = 0; n < 8; ++n) {
        int col = n*8 + tig*2;
        *(float2*)(Xb + m0*64 + col)     = make_float2(acc[n][0], acc[n][1]);
        *(float2*)(Xb + (m0+8)*64 + col) = make_float2(acc[n][2], acc[n][3]);
    }
}

// ===================== kernel C: complex mix via MMA (sums X partials) =====================
__global__ void __launch_bounds__(128) k_mix_mma() {
    __shared__ bf16 sA[16][SPB];
    __shared__ bf16 sBr[64][SPB];
    __shared__ bf16 sBi[64][SPB];
    const int bx = blockIdx.x;
    const int h = bx >> 6, m = bx & 63;
    const int t = threadIdx.x;
    const int wid = t >> 5, lane = t & 31, g = lane >> 2, tig = lane & 3;
    #pragma unroll
    for (int it = 0; it < 8; ++it) {
        int idx = it * 128 + t;
        int bb = idx >> 6, i = idx & 63;
        const float* X0 = g_X + ((bb*8 + h)*2)*8192 + (2*m)*64;
        const float* X1 = X0 + 8192;
        *(u32*)&sA[bb][2*i] = pkbf(X0[i] + X1[i], X0[64 + i] + X1[64 + i]);
    }
    const u32* WR = g_WtR + (h*64 + m)*4096;
    const u32* WI = g_WtI + (h*64 + m)*4096;
    #pragma unroll
    for (int it = 0; it < 32; ++it) {
        int idx = it * 128 + t;
        int i = idx >> 6, o = idx & 63;
        *(u32*)&sBr[o][2*i] = WR[i*64 + o];
        *(u32*)&sBi[o][2*i] = WI[i*64 + o];
    }
    __syncthreads();
    float acc[2][2][4] = {};
    #pragma unroll
    for (int ks = 0; ks < 8; ++ks) {
        const int k0 = ks * 16;
        u32 a[4];
        const bf16* ap = &sA[g][k0 + tig*2];
        a[0] = *(const u32*)ap;
        a[1] = *(const u32*)(ap + 8*SPB);
        a[2] = *(const u32*)(ap + 8);
        a[3] = *(const u32*)(ap + 8*SPB + 8);
        #pragma unroll
        for (int n = 0; n < 2; ++n) {
            int o = wid*16 + n*8 + g;
            const bf16* brp = &sBr[o][k0 + tig*2];
            u32 br[2] = {*(const u32*)brp, *(const u32*)(brp + 8)};
            mma16816(acc[0][n], a, br);
            const bf16* bip = &sBi[o][k0 + tig*2];
            u32 bi2[2] = {*(const u32*)bip, *(const u32*)(bip + 8)};
            mma16816(acc[1][n], a, bi2);
        }
    }
    const float f = (m == 0 ? 1.0f : 2.0f) * (1.0f / 2048.0f);
    u32* Yt32 = (u32*)g_Yt;
    #pragma unroll
    for (int n = 0; n < 2; ++n)
        #pragma unroll
        for (int cc = 0; cc < 2; ++cc) {
            int o = wid*16 + n*8 + tig*2 + cc;
            Yt32[((g*8 + h)*64 + o)*64 + m]     = pkbf(f*acc[0][n][cc],   -f*acc[1][n][cc]);
            Yt32[(((g+8)*8 + h)*64 + o)*64 + m] = pkbf(f*acc[0][n][cc+2], -f*acc[1][n][cc+2]);
        }
}

// ===================== fused D: local attention + inverse DFT, single out write =====================
#define FQ_OFF  0
#define FM_OFF  18432
#define FT_OFF  28800
#define FY_OFF  63616
#define FV_OFF  81024
#define FUSED_SMEM 81280

__global__ void __launch_bounds__(256, 2) k_fused(const float* __restrict__ q,
                                                  float* __restrict__ out) {
    extern __shared__ char dyns[];
    bf16*  sQ  = (bf16*)(dyns + FQ_OFF);    // [128][SPA] rows l
    bf16*  sMt = (bf16*)(dyns + FM_OFF);    // [72][SPA]  rows o (64=ksum, 65-71=0)
    bf16*  sT  = (bf16*)(dyns + FT_OFF);    // [128][SPB] rows l, k=mr
    bf16*  sY  = (bf16*)(dyns + FY_OFF);    // [64][SPB]  rows o, k=mr
    float* svs = (float*)(dyns + FV_OFF);
    const int bh = blockIdx.x;
    const int b = bh >> 3, h = bh & 7;
    const int l0 = blockIdx.y * 128;
    const int t = threadIdx.x;
    const int wid = t >> 5, lane = t & 31, g = lane >> 2, tig = lane & 3;
    const int base = b * NL * HE + h * NE;

    // stage sQ: u32-packed, conflict-free
    #pragma unroll
    for (int it = 0; it < 16; ++it) {
        int idx = it * 256 + t;
        int l = idx >> 5, e2 = idx & 31;
        float2 qv = *(const float2*)(q + base + (l0 + l)*HE + e2*2);
        *(u32*)(sQ + l*SPA + e2*2) = pkbf(qv.x, qv.y);
    }
    // stage sMt = bf16(Mt0 + Mt1)
    const float* M0 = g_Mt + (bh*2)*4096;
    const float* M1 = M0 + 4096;
    #pragma unroll
    for (int it = 0; it < 16; ++it) {
        int idx = it * 256 + t;
        int o = idx >> 6, e = idx & 63;
        sMt[o*SPA + e] = __float2bfloat16(M0[o*64 + e] + M1[o*64 + e]);
    }
    if (t < 64) {
        sMt[64*SPA + t] = __float2bfloat16(g_ksp[(bh*2)*64 + t] + g_ksp[(bh*2+1)*64 + t]);
        svs[t] = g_vsp[(bh*2)*64 + t] + g_vsp[(bh*2+1)*64 + t];
    }
    for (int idx = t; idx < 7*SPA; idx += 256)
        sMt[65*SPA + idx] = __float2bfloat16(0.f);
    // stage sT (u32 copy)
    #pragma unroll
    for (int it = 0; it < 32; ++it) {
        int idx = it * 256 + t;
        int l = idx >> 6, w = idx & 63;
        ((u32*)(sT + l*SPB))[w] = ((const u32*)(g_Tlm + (l0 + l)*128))[w];
    }
    // stage sY (u32 copy)
    #pragma unroll
    for (int it = 0; it < 16; ++it) {
        int idx = it * 256 + t;
        int o = idx >> 6, w = idx & 63;
        ((u32*)(sY + o*SPB))[w] = ((const u32*)(g_Yt + bh*8192 + o*128))[w];
    }
    __syncthreads();

    float accL[9][4] = {};
    float accS[8][4] = {};
    // local: K=64
    #pragma unroll
    for (int ks = 0; ks < 4; ++ks) {
        const int k0 = ks * 16;
        u32 a[4];
        const bf16* ap = sQ + (wid*16 + g)*SPA + k0 + tig*2;
        a[0] = *(const u32*)ap;
        a[1] = *(const u32*)(ap + 8*SPA);
        a[2] = *(const u32*)(ap + 8);
        a[3] = *(const u32*)(ap + 8*SPA + 8);
        #pragma unroll
        for (int n = 0; n < 9; ++n) {
            const bf16* bp = sMt + (n*8 + g)*SPA + k0 + tig*2;
            u32 bfr[2] = {*(const u32*)bp, *(const u32*)(bp + 8)};
            mma16816(accL[n], a, bfr);
        }
    }
    // spec: K=128
    #pragma unroll
    for (int ks = 0; ks < 8; ++ks) {
        const int k0 = ks * 16;
        u32 a[4];
        const bf16* ap = sT + (wid*16 + g)*SPB + k0 + tig*2;
        a[0] = *(const u32*)ap;
        a[1] = *(const u32*)(ap + 8*SPB);
        a[2] = *(const u32*)(ap + 8);
        a[3] = *(const u32*)(ap + 8*SPB + 8);
        #pragma unroll
        for (int n = 0; n < 8; ++n) {
            const bf16* bp = sY + (n*8 + g)*SPB + k0 + tig*2;
            u32 bfr[2] = {*(const u32*)bp, *(const u32*)(bp + 8)};
            mma16816(accS[n], a, bfr);
        }
    }
    // epilogue
    const int r0 = wid*16 + g;
    float z0 = __shfl_sync(0xffffffffu, accL[8][0], lane & ~3);
    float z1 = __shfl_sync(0xffffffffu, accL[8][2], lane & ~3);
    float inv0 = 0.5f / (1024.0f + SCALE_F * z0);
    float inv1 = 0.5f / (1024.0f + SCALE_F * z1);
    #pragma unroll
    for (int n = 0; n < 8; ++n) {
        int col = n*8 + tig*2;
        float2 o0 = make_float2(
            (svs[col]   + SCALE_F*accL[n][0]) * inv0 + accS[n][0],
            (svs[col+1] + SCALE_F*accL[n][1]) * inv0 + accS[n][1]);
        *(float2*)(out + (b*NL + l0 + r0)*HE + h*NE + col) = o0;
        float2 o1 = make_float2(
            (svs[col]   + SCALE_F*accL[n][2]) * inv1 + accS[n][2],
            (svs[col+1] + SCALE_F*accL[n][3]) * inv1 + accS[n][3]);
        *(float2*)(out + (b*NL + l0 + r0 + 8)*HE + h*NE + col) = o1;
    }
}

// ===================== launch =====================
extern "C" void kernel_launch(void* const* d_in, const int* in_sizes, int n_in,
                              void* d_out, int out_size) {
    (void)in_sizes; (void)n_in; (void)out_size;
    const float* q   = (const float*)d_in[0];
    const float* k   = (const float*)d_in[1];
    const float* v   = (const float*)d_in[2];
    // d_in[3] = mask (present -> reference applies no masking); unused
    const float* wre = (const float*)d_in[4];
    const float* wim = (const float*)d_in[5];
    float* out = (float*)d_out;

    static int smem_set = 0;
    if (!smem_set) {
        cudaFuncSetAttribute(k_fused, cudaFuncAttributeMaxDynamicSharedMemorySize, FUSED_SMEM);
        smem_set = 1;
    }

    k_twid     <<<64, 256>>>();
    k_wt       <<<512, 256>>>(wre, wim);
    k_stats_mma<<<dim3(NBH, 2), 256>>>(k, v);
    k_fdft_mma <<<dim3(NBH, 2), 256>>>(q);
    k_mix_mma  <<<512, 128>>>();
    k_fused    <<<dim3(NBH, 8), 256, FUSED_SMEM>>>(q, out);
}

// round 8
// speedup vs baseline: 6.0640x; 1.4168x over previous
#include <cuda_runtime.h>
#include <cuda_bf16.h>

#define NB 16
#define NL 1024
#define NH 8
#define NE 64
#define NM 64
#define NBH (NB*NH)
#define HE 512
#define SCALE_F 3.814697265625e-06f  // 1/(512*512)

typedef unsigned long long u64;
typedef unsigned u32;
typedef __nv_bfloat16 bf16;

// -------- scratch (static device globals) --------
static __device__ float g_Mt[4*NBH*NE*NE];                 // K-split x4 partials of M^T: [bh*4+ky][o][e]
static __device__ float g_ksp[4*NBH*NE];
static __device__ float g_vsp[4*NBH*NE];
static __device__ float g_X[4*NBH*128*64];                 // K-split x4 partials: [bh*4+ky][mr][e]
static __device__ __align__(16) bf16 g_Yt[NBH*64*128];     // [bh][o][mr]: 2m -> f*Yr, 2m+1 -> -f*Yi
static __device__ __align__(16) bf16 g_Tml[128*1024];      // [mr][l]
static __device__ __align__(16) bf16 g_Tlm[1024*128];      // [l][mr]
static __device__ u32 g_WtR[NH*64*64*64];                  // [h][m][i][o] u32=(bf16 Wr, bf16 Wi)
static __device__ u32 g_WtI[NH*64*64*64];                  // [h][m][i][o] u32=(bf16 Wi, bf16 -Wr)

// ---------------- warp MMA helper ----------------
__device__ __forceinline__ void mma16816(float* d, const u32* a, const u32* b) {
    asm volatile(
        "mma.sync.aligned.m16n8k16.row.col.f32.bf16.bf16.f32 "
        "{%0,%1,%2,%3}, {%4,%5,%6,%7}, {%8,%9}, {%0,%1,%2,%3};"
        : "+f"(d[0]), "+f"(d[1]), "+f"(d[2]), "+f"(d[3])
        : "r"(a[0]), "r"(a[1]), "r"(a[2]), "r"(a[3]), "r"(b[0]), "r"(b[1]));
}
__device__ __forceinline__ u32 pkbf(float a, float b) {
    __nv_bfloat162 p = __floats2bfloat162_rn(a, b);   // a -> low
    return *(u32*)&p;
}

#define SPA 72    // bf16 pitch, K<=64 tiles: frag bank = 4g+tig -> conflict-free
#define SPB 136   // bf16 pitch, K=128 tiles: 68 u32/row -> conflict-free

// ===================== twiddle tables =====================
__global__ void __launch_bounds__(256) k_twid() {
    int idx0 = blockIdx.x * 1024 + threadIdx.x;   // 128 blocks x 4 elems
    #pragma unroll
    for (int r = 0; r < 4; ++r) {
        int idx = idx0 + r * 256;
        int l = idx >> 7, mr = idx & 127;
        int m = mr >> 1;
        float s, c;
        sincospif((float)((m * l) & 1023) * (1.0f/512.0f), &s, &c);
        bf16 bv = __float2bfloat16((mr & 1) ? s : c);
        g_Tlm[l*128 + mr] = bv;
        g_Tml[mr*1024 + l] = bv;
    }
}

// ===================== merged front kernel: wt | stats | fdft =====================
// blocks [0,512):    weight transpose
// blocks [512,1024): M^T = v^T k (K-split x4) + exact fp32 ksum/vsum partials
// blocks [1024,1536): forward DFT (K-split x4)
#define FRONT_SMEM 33280

__global__ void __launch_bounds__(256, 4) k_front(const float* __restrict__ wre,
                                                  const float* __restrict__ wim,
                                                  const float* __restrict__ kin,
                                                  const float* __restrict__ vin,
                                                  const float* __restrict__ q) {
    extern __shared__ char dyns[];
    const int bx = blockIdx.x;
    const int t = threadIdx.x;

    if (bx < 512) {
        // ---------------- weight transpose ----------------
        float* smr = (float*)dyns;            // [64][65]
        float* smi = smr + 64*65;             // [64][65]
        const int hi = bx;                    // h*64 + i
        const int h = hi >> 6, i = hi & 63;
        const float* pr = wre + (size_t)hi * 4096;   // [o][m]
        const float* pq = wim + (size_t)hi * 4096;
        #pragma unroll
        for (int it = 0; it < 4; ++it) {
            int idx = it * 256 + t;
            int o = idx >> 4, m4 = idx & 15;
            float4 vr = *(const float4*)(pr + o*64 + m4*4);
            float4 vi = *(const float4*)(pq + o*64 + m4*4);
            smr[o*65 + m4*4+0] = vr.x; smr[o*65 + m4*4+1] = vr.y;
            smr[o*65 + m4*4+2] = vr.z; smr[o*65 + m4*4+3] = vr.w;
            smi[o*65 + m4*4+0] = vi.x; smi[o*65 + m4*4+1] = vi.y;
            smi[o*65 + m4*4+2] = vi.z; smi[o*65 + m4*4+3] = vi.w;
        }
        __syncthreads();
        #pragma unroll
        for (int it = 0; it < 16; ++it) {
            int idx = it * 256 + t;
            int m = idx >> 6, o = idx & 63;
            float wr = smr[o*65 + m], wi = smi[o*65 + m];
            int dst = ((h*64 + m)*64 + i)*64 + o;
            g_WtR[dst] = pkbf(wr, wi);
            g_WtI[dst] = pkbf(wi, -wr);
        }
    } else if (bx < 1024) {
        // ---------------- stats: M^T = v^T k, K-split x4 ----------------
        bf16* sV = (bf16*)dyns;               // [64][SPA]
        bf16* sK = sV + 64*SPA;               // [64][SPA]
        float* red = (float*)(sK + 64*SPA);   // [256]
        const int z = bx - 512;
        const int bh = z >> 2, ky = z & 3;
        const int b = bh >> 3, h = bh & 7;
        const int wid = t >> 5, lane = t & 31, g = lane >> 2, tig = lane & 3;
        const int ot = wid >> 1, eh = wid & 1;
        const int base = b * NL * HE + h * NE + ky * 256 * HE;
        float ka = 0.f, va = 0.f;
        float acc[4][4] = {};
        for (int c = 0; c < 4; ++c) {
            __syncthreads();
            #pragma unroll
            for (int it = 0; it < 16; ++it) {
                int idx = it * 256 + t;
                int s = idx >> 6, o = idx & 63;
                float vv = vin[base + (c*64 + s)*HE + o];
                float kv = kin[base + (c*64 + s)*HE + o];
                sV[o*SPA + s] = __float2bfloat16(vv);
                sK[o*SPA + s] = __float2bfloat16(kv);
                ka += kv; va += vv;
            }
            __syncthreads();
            #pragma unroll
            for (int ks = 0; ks < 4; ++ks) {
                const int k0 = ks * 16;
                u32 a[4];
                const bf16* ap = sV + (ot*16 + g)*SPA + k0 + tig*2;
                a[0] = *(const u32*)ap;
                a[1] = *(const u32*)(ap + 8*SPA);
                a[2] = *(const u32*)(ap + 8);
                a[3] = *(const u32*)(ap + 8*SPA + 8);
                #pragma unroll
                for (int n = 0; n < 4; ++n) {
                    const bf16* bp = sK + (eh*32 + n*8 + g)*SPA + k0 + tig*2;
                    u32 bfr[2] = {*(const u32*)bp, *(const u32*)(bp + 8)};
                    mma16816(acc[n], a, bfr);
                }
            }
        }
        float* Mo = g_Mt + (bh*4 + ky) * 4096;
        const int o0 = ot*16 + g;
        #pragma unroll
        for (int n = 0; n < 4; ++n) {
            int col = eh*32 + n*8 + tig*2;
            *(float2*)(Mo + o0*64 + col)     = make_float2(acc[n][0], acc[n][1]);
            *(float2*)(Mo + (o0+8)*64 + col) = make_float2(acc[n][2], acc[n][3]);
        }
        red[t] = ka; __syncthreads();
        if (t < 64) g_ksp[(bh*4+ky)*64 + t] = red[t] + red[t+64] + red[t+128] + red[t+192];
        __syncthreads();
        red[t] = va; __syncthreads();
        if (t < 64) g_vsp[(bh*4+ky)*64 + t] = red[t] + red[t+64] + red[t+128] + red[t+192];
    } else {
        // ---------------- forward DFT, K-split x4 ----------------
        bf16* sA = (bf16*)dyns;               // [128][SPA]
        bf16* sB = sA + 128*SPA;              // [64][SPA]
        const int z = bx - 1024;
        const int bh = z >> 2, ky = z & 3;
        const int b = bh >> 3, h = bh & 7;
        const int wid = t >> 5, lane = t & 31, g = lane >> 2, tig = lane & 3;
        const int base = b * NL * HE + h * NE;
        float acc[8][4] = {};
        for (int c = 0; c < 4; ++c) {
            const int cc = ky*4 + c;
            __syncthreads();
            #pragma unroll
            for (int it = 0; it < 16; ++it) {
                int idx = it * 256 + t;
                int row = idx >> 5, w = idx & 31;
                ((u32*)(sA + row*SPA))[w] = ((const u32*)(g_Tml + row*1024 + cc*64))[w];
            }
            #pragma unroll
            for (int it = 0; it < 16; ++it) {
                int idx = it * 256 + t;
                int l = idx >> 6, e = idx & 63;
                sB[e*SPA + l] = __float2bfloat16(q[base + (cc*64 + l)*HE + e]);
            }
            __syncthreads();
            #pragma unroll
            for (int ks = 0; ks < 4; ++ks) {
                const int k0 = ks * 16;
                u32 a[4];
                const bf16* ap = sA + (wid*16 + g)*SPA + k0 + tig*2;
                a[0] = *(const u32*)ap;
                a[1] = *(const u32*)(ap + 8*SPA);
                a[2] = *(const u32*)(ap + 8);
                a[3] = *(const u32*)(ap + 8*SPA + 8);
                #pragma unroll
                for (int n = 0; n < 8; ++n) {
                    const bf16* bp = sB + (n*8 + g)*SPA + k0 + tig*2;
                    u32 bfr[2] = {*(const u32*)bp, *(const u32*)(bp + 8)};
                    mma16816(acc[n], a, bfr);
                }
            }
        }
        float* Xb = g_X + (bh*4 + ky) * 8192;
        const int m0 = wid*16 + g;
        #pragma unroll
        for (int n = 0; n < 8; ++n) {
            int col = n*8 + tig*2;
            *(float2*)(Xb + m0*64 + col)     = make_float2(acc[n][0], acc[n][1]);
            *(float2*)(Xb + (m0+8)*64 + col) = make_float2(acc[n][2], acc[n][3]);
        }
    }
}

// ===================== kernel C: complex mix via MMA (sums 4 X partials) =====================
__global__ void __launch_bounds__(128) k_mix_mma() {
    __shared__ bf16 sA[16][SPB];
    __shared__ bf16 sBr[64][SPB];
    __shared__ bf16 sBi[64][SPB];
    const int bx = blockIdx.x;
    const int h = bx >> 6, m = bx & 63;
    const int t = threadIdx.x;
    const int wid = t >> 5, lane = t & 31, g = lane >> 2, tig = lane & 3;
    #pragma unroll
    for (int it = 0; it < 8; ++it) {
        int idx = it * 128 + t;
        int bb = idx >> 6, i = idx & 63;
        const float* X0 = g_X + ((bb*8 + h)*4)*8192 + (2*m)*64;
        float xc = X0[i]      + X0[8192 + i]      + X0[2*8192 + i]      + X0[3*8192 + i];
        float xs = X0[64 + i] + X0[8192 + 64 + i] + X0[2*8192 + 64 + i] + X0[3*8192 + 64 + i];
        *(u32*)&sA[bb][2*i] = pkbf(xc, xs);
    }
    const u32* WR = g_WtR + (h*64 + m)*4096;
    const u32* WI = g_WtI + (h*64 + m)*4096;
    #pragma unroll
    for (int it = 0; it < 32; ++it) {
        int idx = it * 128 + t;
        int i = idx >> 6, o = idx & 63;
        *(u32*)&sBr[o][2*i] = WR[i*64 + o];
        *(u32*)&sBi[o][2*i] = WI[i*64 + o];
    }
    __syncthreads();
    float acc[2][2][4] = {};
    #pragma unroll
    for (int ks = 0; ks < 8; ++ks) {
        const int k0 = ks * 16;
        u32 a[4];
        const bf16* ap = &sA[g][k0 + tig*2];
        a[0] = *(const u32*)ap;
        a[1] = *(const u32*)(ap + 8*SPB);
        a[2] = *(const u32*)(ap + 8);
        a[3] = *(const u32*)(ap + 8*SPB + 8);
        #pragma unroll
        for (int n = 0; n < 2; ++n) {
            int o = wid*16 + n*8 + g;
            const bf16* brp = &sBr[o][k0 + tig*2];
            u32 br[2] = {*(const u32*)brp, *(const u32*)(brp + 8)};
            mma16816(acc[0][n], a, br);
            const bf16* bip = &sBi[o][k0 + tig*2];
            u32 bi2[2] = {*(const u32*)bip, *(const u32*)(bip + 8)};
            mma16816(acc[1][n], a, bi2);
        }
    }
    const float f = (m == 0 ? 1.0f : 2.0f) * (1.0f / 2048.0f);
    u32* Yt32 = (u32*)g_Yt;
    #pragma unroll
    for (int n = 0; n < 2; ++n)
        #pragma unroll
        for (int cc = 0; cc < 2; ++cc) {
            int o = wid*16 + n*8 + tig*2 + cc;
            Yt32[((g*8 + h)*64 + o)*64 + m]     = pkbf(f*acc[0][n][cc],   -f*acc[1][n][cc]);
            Yt32[(((g+8)*8 + h)*64 + o)*64 + m] = pkbf(f*acc[0][n][cc+2], -f*acc[1][n][cc+2]);
        }
}

// ===================== fused D: local attention + inverse DFT, single out write =====================
#define FQ_OFF  0
#define FM_OFF  18432
#define FT_OFF  28800
#define FY_OFF  63616
#define FV_OFF  81024
#define FUSED_SMEM 81280

__global__ void __launch_bounds__(256, 2) k_fused(const float* __restrict__ q,
                                                  float* __restrict__ out) {
    extern __shared__ char dyns[];
    bf16*  sQ  = (bf16*)(dyns + FQ_OFF);    // [128][SPA] rows l
    bf16*  sMt = (bf16*)(dyns + FM_OFF);    // [72][SPA]  rows o (64=ksum, 65-71=0)
    bf16*  sT  = (bf16*)(dyns + FT_OFF);    // [128][SPB] rows l, k=mr
    bf16*  sY  = (bf16*)(dyns + FY_OFF);    // [64][SPB]  rows o, k=mr
    float* svs = (float*)(dyns + FV_OFF);
    const int bh = blockIdx.x;
    const int b = bh >> 3, h = bh & 7;
    const int l0 = blockIdx.y * 128;
    const int t = threadIdx.x;
    const int wid = t >> 5, lane = t & 31, g = lane >> 2, tig = lane & 3;
    const int base = b * NL * HE + h * NE;

    #pragma unroll
    for (int it = 0; it < 16; ++it) {
        int idx = it * 256 + t;
        int l = idx >> 5, e2 = idx & 31;
        float2 qv = *(const float2*)(q + base + (l0 + l)*HE + e2*2);
        *(u32*)(sQ + l*SPA + e2*2) = pkbf(qv.x, qv.y);
    }
    const float* Mp = g_Mt + (bh*4)*4096;
    #pragma unroll
    for (int it = 0; it < 16; ++it) {
        int idx = it * 256 + t;
        int o = idx >> 6, e = idx & 63;
        float mv = Mp[o*64 + e] + Mp[4096 + o*64 + e] + Mp[2*4096 + o*64 + e] + Mp[3*4096 + o*64 + e];
        sMt[o*SPA + e] = __float2bfloat16(mv);
    }
    if (t < 64) {
        const float* kp = g_ksp + (bh*4)*64;
        const float* vp = g_vsp + (bh*4)*64;
        sMt[64*SPA + t] = __float2bfloat16(kp[t] + kp[64+t] + kp[128+t] + kp[192+t]);
        svs[t] = vp[t] + vp[64+t] + vp[128+t] + vp[192+t];
    }
    for (int idx = t; idx < 7*SPA; idx += 256)
        sMt[65*SPA + idx] = __float2bfloat16(0.f);
    #pragma unroll
    for (int it = 0; it < 32; ++it) {
        int idx = it * 256 + t;
        int l = idx >> 6, w = idx & 63;
        ((u32*)(sT + l*SPB))[w] = ((const u32*)(g_Tlm + (l0 + l)*128))[w];
    }
    #pragma unroll
    for (int it = 0; it < 16; ++it) {
        int idx = it * 256 + t;
        int o = idx >> 6, w = idx & 63;
        ((u32*)(sY + o*SPB))[w] = ((const u32*)(g_Yt + bh*8192 + o*128))[w];
    }
    __syncthreads();

    float accL[9][4] = {};
    float accS[8][4] = {};
    #pragma unroll
    for (int ks = 0; ks < 4; ++ks) {
        const int k0 = ks * 16;
        u32 a[4];
        const bf16* ap = sQ + (wid*16 + g)*SPA + k0 + tig*2;
        a[0] = *(const u32*)ap;
        a[1] = *(const u32*)(ap + 8*SPA);
        a[2] = *(const u32*)(ap + 8);
        a[3] = *(const u32*)(ap + 8*SPA + 8);
        #pragma unroll
        for (int n = 0; n < 9; ++n) {
            const bf16* bp = sMt + (n*8 + g)*SPA + k0 + tig*2;
            u32 bfr[2] = {*(const u32*)bp, *(const u32*)(bp + 8)};
            mma16816(accL[n], a, bfr);
        }
    }
    #pragma unroll
    for (int ks = 0; ks < 8; ++ks) {
        const int k0 = ks * 16;
        u32 a[4];
        const bf16* ap = sT + (wid*16 + g)*SPB + k0 + tig*2;
        a[0] = *(const u32*)ap;
        a[1] = *(const u32*)(ap + 8*SPB);
        a[2] = *(const u32*)(ap + 8);
        a[3] = *(const u32*)(ap + 8*SPB + 8);
        #pragma unroll
        for (int n = 0; n < 8; ++n) {
            const bf16* bp = sY + (n*8 + g)*SPB + k0 + tig*2;
            u32 bfr[2] = {*(const u32*)bp, *(const u32*)(bp + 8)};
            mma16816(accS[n], a, bfr);
        }
    }
    const int r0 = wid*16 + g;
    float z0 = __shfl_sync(0xffffffffu, accL[8][0], lane & ~3);
    float z1 = __shfl_sync(0xffffffffu, accL[8][2], lane & ~3);
    float inv0 = 0.5f / (1024.0f + SCALE_F * z0);
    float inv1 = 0.5f / (1024.0f + SCALE_F * z1);
    #pragma unroll
    for (int n = 0; n < 8; ++n) {
        int col = n*8 + tig*2;
        float2 o0 = make_float2(
            (svs[col]   + SCALE_F*accL[n][0]) * inv0 + accS[n][0],
            (svs[col+1] + SCALE_F*accL[n][1]) * inv0 + accS[n][1]);
        *(float2*)(out + (b*NL + l0 + r0)*HE + h*NE + col) = o0;
        float2 o1 = make_float2(
            (svs[col]   + SCALE_F*accL[n][2]) * inv1 + accS[n][2],
            (svs[col+1] + SCALE_F*accL[n][3]) * inv1 + accS[n][3]);
        *(float2*)(out + (b*NL + l0 + r0 + 8)*HE + h*NE + col) = o1;
    }
}

// ===================== launch =====================
extern "C" void kernel_launch(void* const* d_in, const int* in_sizes, int n_in,
                              void* d_out, int out_size) {
    (void)in_sizes; (void)n_in; (void)out_size;
    const float* q   = (const float*)d_in[0];
    const float* k   = (const float*)d_in[1];
    const float* v   = (const float*)d_in[2];
    // d_in[3] = mask (present -> reference applies no masking); unused
    const float* wre = (const float*)d_in[4];
    const float* wim = (const float*)d_in[5];
    float* out = (float*)d_out;

    static int smem_set = 0;
    if (!smem_set) {
        cudaFuncSetAttribute(k_fused, cudaFuncAttributeMaxDynamicSharedMemorySize, FUSED_SMEM);
        smem_set = 1;
    }

    k_twid   <<<128, 256>>>();
    k_front  <<<1536, 256, FRONT_SMEM>>>(wre, wim, k, v, q);
    k_mix_mma<<<512, 128>>>();
    k_fused  <<<dim3(NBH, 8), 256, FUSED_SMEM>>>(q, out);
}